// round 1
// baseline (speedup 1.0000x reference)
#include <cuda_runtime.h>
#include <math.h>

#define TOKENS 4096
#define DDIM   1024

// scratch: per-token scalar s[t] (no cudaMalloc allowed)
__device__ float g_s[TOKENS];

__device__ __forceinline__ float softplusf(float z) {
    // log1p(exp(z)) with overflow guard; exp underflow gives correct limit 0.
    if (z > 20.0f) return z;
    return log1pf(expf(z));
}

// ---------------------------------------------------------------------------
// Kernel 1: s[t] = sum_n (x@W2^T + b2)[t,n] * (x@W3^T + b3)[t,n]
// Block = 32 tokens, 256 threads. Thread: token = tid&31, group g = tid>>5
// owns 4 of the 32 outputs (rows 0..15 = W2/Bm, rows 16..31 = W3/Cm).
// ---------------------------------------------------------------------------
__global__ __launch_bounds__(256) void s_kernel(
    const float* __restrict__ x,
    const float* __restrict__ W2, const float* __restrict__ b2,
    const float* __restrict__ W3, const float* __restrict__ b3)
{
    __shared__ float sx[64][33];   // x tile transposed: [k][token], padded
    __shared__ float sw[32][64];   // weight tile: [n][k]
    __shared__ float sout[32][33]; // [token][n]

    const int tid = threadIdx.x;
    const int t0  = blockIdx.x * 32;
    const int tok = tid & 31;
    const int g   = tid >> 5;

    float acc[4] = {0.f, 0.f, 0.f, 0.f};

    for (int k0 = 0; k0 < DDIM; k0 += 64) {
        // load x tile (32 tokens x 64 k) transposed into sx
        {
            int f4 = tid;
            #pragma unroll
            for (int it = 0; it < 2; ++it) {
                int tk = f4 >> 4;      // token 0..31
                int c4 = f4 & 15;      // float4 column
                float4 v = *reinterpret_cast<const float4*>(
                    &x[(size_t)(t0 + tk) * DDIM + k0 + c4 * 4]);
                sx[c4 * 4 + 0][tk] = v.x;
                sx[c4 * 4 + 1][tk] = v.y;
                sx[c4 * 4 + 2][tk] = v.z;
                sx[c4 * 4 + 3][tk] = v.w;
                f4 += 256;
            }
        }
        // load weight tile: rows 0..15 from W2, rows 16..31 from W3
        {
            int f4 = tid;
            #pragma unroll
            for (int it = 0; it < 2; ++it) {
                int n  = f4 >> 4;
                int c4 = f4 & 15;
                const float* src = (n < 16) ? &W2[(size_t)n * DDIM]
                                            : &W3[(size_t)(n - 16) * DDIM];
                *reinterpret_cast<float4*>(&sw[n][c4 * 4]) =
                    *reinterpret_cast<const float4*>(&src[k0 + c4 * 4]);
                f4 += 256;
            }
        }
        __syncthreads();
        #pragma unroll 8
        for (int k = 0; k < 64; ++k) {
            float xv = sx[k][tok];
            #pragma unroll
            for (int j = 0; j < 4; ++j)
                acc[j] += xv * sw[g * 4 + j][k];
        }
        __syncthreads();
    }

    #pragma unroll
    for (int j = 0; j < 4; ++j) sout[tok][g * 4 + j] = acc[j];
    __syncthreads();

    if (tid < 32) {
        float s = 0.f;
        #pragma unroll
        for (int n = 0; n < 16; ++n)
            s += (sout[tid][n] + b2[n]) * (sout[tid][16 + n] + b3[n]);
        g_s[t0 + tid] = s;
    }
}

// ---------------------------------------------------------------------------
// Kernel 2: fused GEMM + epilogue
//   y[t,d] = x[t,d] * softplus( (x @ W1^T)[t,d] + b1[d] ) * s[t]
// 128x128 block tile, BK=8, 256 threads, 8x8 microtile (split 4+4 layout),
// register double-buffered global loads, transposed smem tiles.
// ---------------------------------------------------------------------------
#define BM 128
#define BN 128
#define BK 8

__global__ __launch_bounds__(256) void fused_gemm_kernel(
    const float* __restrict__ x,
    const float* __restrict__ W1,
    const float* __restrict__ b1,
    float* __restrict__ y)
{
    __shared__ float sA[BK][BM + 4];   // [8][132] x tile transposed
    __shared__ float sB[BK][BN + 4];   // [8][132] W1 tile transposed

    const int tid   = threadIdx.x;
    const int cx    = tid & 15;        // column group (B/N side)
    const int cy    = tid >> 4;        // row group    (A/M side)
    const int rbase = blockIdx.y * BM;
    const int cbase = blockIdx.x * BN;

    // global->smem load mapping: 256 float4 per tile per operand
    const int lrow = tid >> 1;           // 0..127
    const int lc4  = (tid & 1) * 4;      // 0 or 4

    const float* gA = &x [(size_t)(rbase + lrow) * DDIM + lc4];
    const float* gB = &W1[(size_t)(cbase + lrow) * DDIM + lc4];

    float acc[8][8];
    #pragma unroll
    for (int i = 0; i < 8; ++i)
        #pragma unroll
        for (int j = 0; j < 8; ++j)
            acc[i][j] = 0.f;

    // prologue: tile 0
    {
        float4 pa = *reinterpret_cast<const float4*>(gA);
        float4 pb = *reinterpret_cast<const float4*>(gB);
        sA[lc4 + 0][lrow] = pa.x; sA[lc4 + 1][lrow] = pa.y;
        sA[lc4 + 2][lrow] = pa.z; sA[lc4 + 3][lrow] = pa.w;
        sB[lc4 + 0][lrow] = pb.x; sB[lc4 + 1][lrow] = pb.y;
        sB[lc4 + 2][lrow] = pb.z; sB[lc4 + 3][lrow] = pb.w;
    }
    __syncthreads();

    const int NT = DDIM / BK;  // 128
    for (int t = 0; t < NT; ++t) {
        float4 na, nb;
        if (t + 1 < NT) {
            na = *reinterpret_cast<const float4*>(gA + (t + 1) * BK);
            nb = *reinterpret_cast<const float4*>(gB + (t + 1) * BK);
        }
        #pragma unroll
        for (int k = 0; k < BK; ++k) {
            float fa[8], fb[8];
            *reinterpret_cast<float4*>(&fa[0]) =
                *reinterpret_cast<const float4*>(&sA[k][cy * 4]);
            *reinterpret_cast<float4*>(&fa[4]) =
                *reinterpret_cast<const float4*>(&sA[k][64 + cy * 4]);
            *reinterpret_cast<float4*>(&fb[0]) =
                *reinterpret_cast<const float4*>(&sB[k][cx * 4]);
            *reinterpret_cast<float4*>(&fb[4]) =
                *reinterpret_cast<const float4*>(&sB[k][64 + cx * 4]);
            #pragma unroll
            for (int i = 0; i < 8; ++i)
                #pragma unroll
                for (int j = 0; j < 8; ++j)
                    acc[i][j] += fa[i] * fb[j];
        }
        __syncthreads();
        if (t + 1 < NT) {
            sA[lc4 + 0][lrow] = na.x; sA[lc4 + 1][lrow] = na.y;
            sA[lc4 + 2][lrow] = na.z; sA[lc4 + 3][lrow] = na.w;
            sB[lc4 + 0][lrow] = nb.x; sB[lc4 + 1][lrow] = nb.y;
            sB[lc4 + 2][lrow] = nb.z; sB[lc4 + 3][lrow] = nb.w;
            __syncthreads();
        }
    }

    // epilogue: y = x * softplus(acc + b1) * s
    #pragma unroll
    for (int ih = 0; ih < 2; ++ih) {
        #pragma unroll
        for (int i = 0; i < 4; ++i) {
            const int r = rbase + ih * 64 + cy * 4 + i;
            const float sv = g_s[r];
            const float* xrow = &x[(size_t)r * DDIM];
            float*       yrow = &y[(size_t)r * DDIM];
            #pragma unroll
            for (int jh = 0; jh < 2; ++jh) {
                const int c = cbase + jh * 64 + cx * 4;
                float4 xv = *reinterpret_cast<const float4*>(&xrow[c]);
                float4 bv = *reinterpret_cast<const float4*>(&b1[c]);
                float4 o;
                o.x = xv.x * softplusf(acc[ih * 4 + i][jh * 4 + 0] + bv.x) * sv;
                o.y = xv.y * softplusf(acc[ih * 4 + i][jh * 4 + 1] + bv.y) * sv;
                o.z = xv.z * softplusf(acc[ih * 4 + i][jh * 4 + 2] + bv.z) * sv;
                o.w = xv.w * softplusf(acc[ih * 4 + i][jh * 4 + 3] + bv.w) * sv;
                *reinterpret_cast<float4*>(&yrow[c]) = o;
            }
        }
    }
}

extern "C" void kernel_launch(void* const* d_in, const int* in_sizes, int n_in,
                              void* d_out, int out_size)
{
    const float* x  = (const float*)d_in[0];
    const float* W1 = (const float*)d_in[1];
    const float* b1 = (const float*)d_in[2];
    const float* W2 = (const float*)d_in[3];
    const float* b2 = (const float*)d_in[4];
    const float* W3 = (const float*)d_in[5];
    const float* b3 = (const float*)d_in[6];
    // d_in[7] = A is mathematically dead (multiplies zero-initialized h).
    float* y = (float*)d_out;

    s_kernel<<<TOKENS / 32, 256>>>(x, W2, b2, W3, b3);

    dim3 grid(DDIM / BN, TOKENS / BM);  // (8, 32) = 256 blocks
    fused_gemm_kernel<<<grid, 256>>>(x, W1, b1, y);
}